// round 6
// baseline (speedup 1.0000x reference)
#include <cuda_runtime.h>

#define NSAMP 16384
#define PTS   20
#define DIM   128
#define KNN   5
#define NANCH (NSAMP * PTS)          // 327,680 anchors
#define EDGES (NANCH * KNN)          // 1,638,400 edges per output
#define NTHREADS 128

__global__ void __launch_bounds__(NTHREADS)
knn_kernel(const float* __restrict__ x, float* __restrict__ out, int cap) {
    const int w = blockIdx.x * NTHREADS + threadIdx.x;   // anchor id
    if (w >= NANCH) return;
    const int n = w / PTS;
    const int p = w - n * PTS;

    // sample base: n * 20*128 floats = n * 10240 B -> float4 aligned
    const float4* xs = reinterpret_cast<const float4*>(x) + (size_t)n * (PTS * DIM / 4);

    // own row -> registers
    float4 xp[DIM / 4];
    #pragma unroll
    for (int e = 0; e < DIM / 4; e++) xp[e] = xs[p * (DIM / 4) + e];

    // ||xp||^2 (4 chains, same shape as dot accumulation)
    float s0 = 0.f, s1 = 0.f, s2 = 0.f, s3 = 0.f;
    #pragma unroll
    for (int e = 0; e < DIM / 4; e++) {
        s0 = fmaf(xp[e].x, xp[e].x, s0);
        s1 = fmaf(xp[e].y, xp[e].y, s1);
        s2 = fmaf(xp[e].z, xp[e].z, s2);
        s3 = fmaf(xp[e].w, xp[e].w, s3);
    }
    const float sqp = (s0 + s1) + (s2 + s3);

    // stream 20 candidates; exact u64-keyed branchless top-5 (self excluded)
    unsigned long long keys[KNN];
    #pragma unroll
    for (int m = 0; m < KNN; m++) keys[m] = 0xFFFFFFFFFFFFFFFFull;

    #pragma unroll 1
    for (int q = 0; q < PTS; q++) {
        const float4* xq = xs + q * (DIM / 4);
        float a0 = 0.f, a1 = 0.f, a2 = 0.f, a3 = 0.f;
        float b0 = 0.f, b1 = 0.f, b2 = 0.f, b3 = 0.f;
        #pragma unroll
        for (int e = 0; e < DIM / 4; e++) {
            float4 v = xq[e];
            a0 = fmaf(xp[e].x, v.x, a0);
            a1 = fmaf(xp[e].y, v.y, a1);
            a2 = fmaf(xp[e].z, v.z, a2);
            a3 = fmaf(xp[e].w, v.w, a3);
            b0 = fmaf(v.x, v.x, b0);
            b1 = fmaf(v.y, v.y, b1);
            b2 = fmaf(v.z, v.z, b2);
            b3 = fmaf(v.w, v.w, b3);
        }
        const float dot = (a0 + a1) + (a2 + a3);
        const float sqq = (b0 + b1) + (b2 + b3);
        const float d2  = fmaxf(sqp + sqq - 2.0f * dot, 0.0f);   // reference clamp

        unsigned long long key = (q == p)
            ? 0xFFFFFFFFFFFFFFFFull
            : (((unsigned long long)__float_as_uint(d2) << 32) | (unsigned)q);
        #pragma unroll
        for (int m = 0; m < KNN; m++) {
            unsigned long long lo = (keys[m] < key) ? keys[m] : key;
            unsigned long long hi = (keys[m] < key) ? key : keys[m];
            keys[m] = lo;
            key = hi;
        }
    }

    // emit as FLOAT32 values: U in [0, EDGES), V in [EDGES, 2*EDGES)
    const int ob = w * KNN;
    const float pf = (float)p;
    #pragma unroll
    for (int r = 0; r < KNN; r++) {
        int iu = ob + r;
        int iv = EDGES + ob + r;
        if (iu < cap) out[iu] = pf;
        if (iv < cap) out[iv] = (float)(int)(keys[r] & 0xFFFFFFFFull);
    }
}

extern "C" void kernel_launch(void* const* d_in, const int* in_sizes, int n_in,
                              void* d_out, int out_size) {
    const float* x = (const float*)d_in[0];
    float* out = (float*)d_out;

    // out_size used ONLY as a defensive cap; all geometry is hardcoded.
    int cap = 2 * EDGES;
    if (out_size > 0 && out_size < 2 * EDGES) cap = out_size;

    const int grid = (NANCH + NTHREADS - 1) / NTHREADS;   // 2560
    knn_kernel<<<grid, NTHREADS>>>(x, out, cap);
}

// round 7
// speedup vs baseline: 2.3387x; 2.3387x over previous
#include <cuda_runtime.h>

#define NSAMP 16384
#define PTS   20
#define DIM   128
#define KNN   5
#define NANCH (NSAMP * PTS)          // 327,680 anchors
#define EDGES (NANCH * KNN)          // 1,638,400 edges per output

#define SPB 4                        // samples per block
#define NTH 96                       // 3 warps; first 80 threads compute
#define RSTRIDE 132                  // words per row (pad: conflict-free lane-row access)
#define SAMP_STRIDE (PTS * RSTRIDE)  // 2640 words per sample
#define SMEM_X (SPB * SAMP_STRIDE)   // 10560 words
#define SMEM_FLOATS (SMEM_X + SPB * PTS)  // + norms = 10640 words = 42,560 B

__device__ __forceinline__ void fma2(unsigned long long &acc,
                                     unsigned long long a,
                                     unsigned long long b) {
    asm("fma.rn.f32x2 %0, %1, %2, %0;" : "+l"(acc) : "l"(a), "l"(b));
}

// (a0+a1) + (a2+a3): identical summation order to the round-6 scalar version
__device__ __forceinline__ float chainsum(unsigned long long acc01,
                                          unsigned long long acc23) {
    float2 lo = *reinterpret_cast<float2*>(&acc01);   // (a0, a1)
    float2 hi = *reinterpret_cast<float2*>(&acc23);   // (a2, a3)
    return (lo.x + lo.y) + (hi.x + hi.y);
}

__global__ void __launch_bounds__(NTH, 4)
knn_kernel(const float* __restrict__ x, float* __restrict__ out, int cap) {
    __shared__ __align__(16) float sm[SMEM_FLOATS];
    float* snorm = &sm[SMEM_X];

    const int tid = threadIdx.x;
    const int bs0 = blockIdx.x * SPB;   // first sample of this block (grid exact)

    // ---- Stage 4 samples gmem -> smem (coalesced float4) ----
    {
        const float4* xin = reinterpret_cast<const float4*>(x)
                          + (size_t)bs0 * (PTS * DIM / 4);
        #pragma unroll
        for (int t = tid; t < SPB * PTS * (DIM / 4); t += NTH) {
            int rc  = t >> 5;                 // row 0..79
            int e   = t & 31;                 // float4 idx in row
            int s   = rc / PTS;
            int row = rc - s * PTS;
            float4 v = xin[(size_t)rc * 32 + e];
            *reinterpret_cast<float4*>(&sm[s * SAMP_STRIDE + row * RSTRIDE + e * 4]) = v;
        }
    }
    __syncthreads();

    const bool active = (tid < SPB * PTS);
    const int s = active ? (tid / PTS) : 0;
    const int p = active ? (tid - s * PTS) : 0;

    // ---- Own row -> registers as f32x2 pairs; norm with identical chains ----
    unsigned long long xp[DIM / 2];     // xp[2e]=(d0,d1), xp[2e+1]=(d2,d3)
    float sqp = 0.0f;
    if (active) {
        const ulonglong2* xrow =
            reinterpret_cast<const ulonglong2*>(&sm[s * SAMP_STRIDE + p * RSTRIDE]);
        unsigned long long n01 = 0ull, n23 = 0ull;
        #pragma unroll
        for (int e = 0; e < DIM / 4; e++) {
            ulonglong2 v = xrow[e];
            xp[2 * e]     = v.x;
            xp[2 * e + 1] = v.y;
            fma2(n01, v.x, v.x);
            fma2(n23, v.y, v.y);
        }
        sqp = chainsum(n01, n23);
        snorm[s * PTS + p] = sqp;
    }
    __syncthreads();
    if (!active) return;

    // ---- Stream 20 candidates; exact u64-keyed branchless top-5 ----
    unsigned long long keys[KNN];
    #pragma unroll
    for (int m = 0; m < KNN; m++) keys[m] = 0xFFFFFFFFFFFFFFFFull;

    const float* sbase = &sm[s * SAMP_STRIDE];
    #pragma unroll 1
    for (int q = 0; q < PTS; q++) {
        const ulonglong2* xq =
            reinterpret_cast<const ulonglong2*>(sbase + q * RSTRIDE);
        unsigned long long a01 = 0ull, a23 = 0ull;
        #pragma unroll
        for (int e = 0; e < DIM / 4; e++) {
            ulonglong2 v = xq[e];       // broadcast across same-sample lanes
            fma2(a01, xp[2 * e],     v.x);
            fma2(a23, xp[2 * e + 1], v.y);
        }
        const float dot = chainsum(a01, a23);
        const float sqq = snorm[s * PTS + q];
        const float d2  = fmaxf(sqp + sqq - 2.0f * dot, 0.0f);   // reference clamp

        unsigned long long key = (q == p)
            ? 0xFFFFFFFFFFFFFFFFull
            : (((unsigned long long)__float_as_uint(d2) << 32) | (unsigned)q);
        #pragma unroll
        for (int m = 0; m < KNN; m++) {
            unsigned long long lo = (keys[m] < key) ? keys[m] : key;
            unsigned long long hi = (keys[m] < key) ? key : keys[m];
            keys[m] = lo;
            key = hi;
        }
    }

    // ---- Emit float32: U in [0, EDGES), V in [EDGES, 2*EDGES) ----
    const int w  = bs0 * PTS + s * PTS + p;   // global anchor id
    const int ob = w * KNN;
    const float pf = (float)p;
    #pragma unroll
    for (int r = 0; r < KNN; r++) {
        int iu = ob + r;
        int iv = EDGES + ob + r;
        if (iu < cap) out[iu] = pf;
        if (iv < cap) out[iv] = (float)(int)(keys[r] & 0xFFFFFFFFull);
    }
}

extern "C" void kernel_launch(void* const* d_in, const int* in_sizes, int n_in,
                              void* d_out, int out_size) {
    const float* x = (const float*)d_in[0];
    float* out = (float*)d_out;

    int cap = 2 * EDGES;
    if (out_size > 0 && out_size < 2 * EDGES) cap = out_size;

    const int grid = NSAMP / SPB;    // 4096, exact
    knn_kernel<<<grid, NTH>>>(x, out, cap);
}